// round 4
// baseline (speedup 1.0000x reference)
#include <cuda_runtime.h>

// ---------------- problem constants ----------------
#define T_WIN 4
#define BATCH 128
#define SEQ   64
#define BSROWS 8192           // BATCH*SEQ
#define DIN   3136
#define FUS   512
#define HID   512
#define NLAST 18

// ---------------- scratch (device globals; no allocations allowed) ----------------
__device__ float         g_dist [(size_t)T_WIN * BSROWS * FUS];   // 64 MiB
__device__ float         g_prox [T_WIN * BATCH * FUS];
__device__ float         g_trunk[T_WIN * BATCH * FUS];
__device__ float         g_p    [BATCH * FUS];
__device__ float         g_ts   [BATCH * FUS];
__device__ float         g_d    [BSROWS * FUS];                   // 16 MiB
__device__ float         g_soma [BSROWS * FUS];                   // 16 MiB
__device__ unsigned char g_spk  [BSROWS * FUS];                   // 4 MiB
__device__ float         g_lif  [BSROWS * HID];                   // 16 MiB
__device__ unsigned char g_hs   [BSROWS * HID];                   // 4 MiB
__device__ float         g_outacc[BSROWS * NLAST];

// ---------------- generic fp32 SGEMM: C[M,N] = A[M,K] @ B[K,N], row-major ----------------
template<int BM, int BN, int BK, int TM, int TN>
__global__ __launch_bounds__((BM/TM)*(BN/TN))
void sgemm_kernel(const float* __restrict__ A, const float* __restrict__ B,
                  float* __restrict__ C, int M, int N, int K)
{
    const int NT = (BM/TM)*(BN/TN);
    __shared__ float As[BK][BM + 1];   // +1 pad: reduce STS bank conflicts
    __shared__ float Bs[BK][BN];

    const int tid  = threadIdx.x;
    const int tcol = tid % (BN/TN);
    const int trow = tid / (BN/TN);

    const float* Ab = A + (size_t)blockIdx.y * BM * K;
    const float* Bb = B + blockIdx.x * BN;

    float acc[TM][TN];
#pragma unroll
    for (int i = 0; i < TM; i++)
#pragma unroll
        for (int j = 0; j < TN; j++) acc[i][j] = 0.0f;

    for (int k0 = 0; k0 < K; k0 += BK) {
        // A tile: BM x BK, vectorized along K, stored transposed
#pragma unroll
        for (int i = tid; i < BM*BK/4; i += NT) {
            int row = i / (BK/4);
            int kc  = (i % (BK/4)) * 4;
            float4 v = *(const float4*)(Ab + (size_t)row * K + k0 + kc);
            As[kc+0][row] = v.x; As[kc+1][row] = v.y;
            As[kc+2][row] = v.z; As[kc+3][row] = v.w;
        }
        // B tile: BK x BN, vectorized along N
#pragma unroll
        for (int i = tid; i < BK*BN/4; i += NT) {
            int row = i / (BN/4);
            int nc  = (i % (BN/4)) * 4;
            *(float4*)(&Bs[row][nc]) = *(const float4*)(Bb + (size_t)(k0+row) * N + nc);
        }
        __syncthreads();

#pragma unroll
        for (int kk = 0; kk < BK; kk++) {
            float ar[TM], br[TN];
#pragma unroll
            for (int ii = 0; ii < TM; ii++) ar[ii] = As[kk][trow*TM + ii];
#pragma unroll
            for (int jj = 0; jj < TN; jj++) br[jj] = Bs[kk][tcol*TN + jj];
#pragma unroll
            for (int ii = 0; ii < TM; ii++)
#pragma unroll
                for (int jj = 0; jj < TN; jj++)
                    acc[ii][jj] = fmaf(ar[ii], br[jj], acc[ii][jj]);
        }
        __syncthreads();
    }

    float* Cb = C + (size_t)(blockIdx.y*BM + trow*TM) * N + blockIdx.x*BN + tcol*TN;
#pragma unroll
    for (int ii = 0; ii < TM; ii++)
#pragma unroll
        for (int jj = 0; jj < TN; jj++)
            Cb[(size_t)ii * N + jj] = acc[ii][jj];
}

// ---------------- per-step: proximal / trunk LIF state (per [B,F]) ----------------
__global__ void lif_pt_kernel(const float* __restrict__ prox_t,
                              const float* __restrict__ trunk_t,
                              float* __restrict__ p, float* __restrict__ ts, int first)
{
    int i = blockIdx.x * blockDim.x + threadIdx.x;
    if (i >= BATCH * FUS) return;
    float pv = first ? 0.0f : p[i];
    float tv = first ? 0.0f : ts[i];
    // exactly mirror reference rounding: v + (x - v) / 2
    pv = __fadd_rn(pv, __fmul_rn(__fsub_rn(prox_t[i],  pv), 0.5f));
    tv = __fadd_rn(tv, __fmul_rn(__fsub_rn(trunk_t[i], tv), 0.5f));
    p[i]  = pv;
    ts[i] = tv;
}

// ---------------- per-step: dendrite + soma LIF + spike (float4 over [B,S,F]) ----------------
__global__ void lif_soma_kernel(const float* __restrict__ dist_t,
                                const float* __restrict__ p, const float* __restrict__ ts,
                                float* __restrict__ d, float* __restrict__ soma,
                                unsigned char* __restrict__ spk, int first)
{
    int i = blockIdx.x * blockDim.x + threadIdx.x;     // over BSROWS*FUS/4
    if (i >= BSROWS * FUS / 4) return;
    int fi4 = i & (FUS/4 - 1);      // f/4
    int n   = i >> 7;               // / (FUS/4)
    int b   = n >> 6;               // / SEQ

    float4 dd = ((const float4*)dist_t)[i];
    float4 dv, sv;
    if (first) { dv = make_float4(0,0,0,0); sv = make_float4(0,0,0,0); }
    else       { dv = ((const float4*)d)[i]; sv = ((const float4*)soma)[i]; }
    float4 pv = ((const float4*)p)[b * (FUS/4) + fi4];
    float4 tv = ((const float4*)ts)[b * (FUS/4) + fi4];

    uchar4 sp;
#define LIF_STEP(c)                                                            \
    {                                                                          \
        dv.c = __fadd_rn(dv.c, __fmul_rn(__fsub_rn(dd.c, dv.c), 0.5f));        \
        float u = __fsub_rn(__fadd_rn(__fmul_rn(pv.c, dv.c), tv.c), sv.c);     \
        sv.c = __fadd_rn(sv.c, __fmul_rn(u, 0.5f));                            \
        sp.c = (sv.c >= 0.5f) ? 1 : 0;                                         \
        if (sp.c) sv.c = 0.0f;                                                 \
    }
    LIF_STEP(x) LIF_STEP(y) LIF_STEP(z) LIF_STEP(w)
#undef LIF_STEP

    ((float4*)d)[i]    = dv;
    ((float4*)soma)[i] = sv;
    ((uchar4*)spk)[i]  = sp;
}

// ---------------- per-step: h = spk@W1 + b1, hidden LIF + spike, fused ----------------
template<int BM, int BN, int BK, int TM, int TN>
__global__ __launch_bounds__((BM/TM)*(BN/TN))
void h_lif_kernel(const unsigned char* __restrict__ spkA, const float* __restrict__ W1,
                  const float* __restrict__ b1, float* __restrict__ lif,
                  unsigned char* __restrict__ hs, int first)
{
    const int NT = (BM/TM)*(BN/TN);
    const int N = HID, K = FUS;
    __shared__ float As[BK][BM + 1];
    __shared__ float Bs[BK][BN];

    const int tid  = threadIdx.x;
    const int tcol = tid % (BN/TN);
    const int trow = tid / (BN/TN);

    const unsigned char* Ab = spkA + (size_t)blockIdx.y * BM * K;
    const float* Bb = W1 + blockIdx.x * BN;

    float acc[TM][TN];
#pragma unroll
    for (int i = 0; i < TM; i++)
#pragma unroll
        for (int j = 0; j < TN; j++) acc[i][j] = 0.0f;

    for (int k0 = 0; k0 < K; k0 += BK) {
        // A tile (bytes -> floats)
#pragma unroll
        for (int i = tid; i < BM*BK/8; i += NT) {
            int row = i / (BK/8);
            int kc  = (i % (BK/8)) * 8;
            uint2 v = *(const uint2*)(Ab + (size_t)row * K + k0 + kc);
            const unsigned char* pb = (const unsigned char*)&v;
#pragma unroll
            for (int j = 0; j < 8; j++) As[kc + j][row] = (float)pb[j];
        }
#pragma unroll
        for (int i = tid; i < BK*BN/4; i += NT) {
            int row = i / (BN/4);
            int nc  = (i % (BN/4)) * 4;
            *(float4*)(&Bs[row][nc]) = *(const float4*)(Bb + (size_t)(k0+row) * N + nc);
        }
        __syncthreads();

#pragma unroll
        for (int kk = 0; kk < BK; kk++) {
            float ar[TM], br[TN];
#pragma unroll
            for (int ii = 0; ii < TM; ii++) ar[ii] = As[kk][trow*TM + ii];
#pragma unroll
            for (int jj = 0; jj < TN; jj++) br[jj] = Bs[kk][tcol*TN + jj];
#pragma unroll
            for (int ii = 0; ii < TM; ii++)
#pragma unroll
                for (int jj = 0; jj < TN; jj++)
                    acc[ii][jj] = fmaf(ar[ii], br[jj], acc[ii][jj]);
        }
        __syncthreads();
    }

    // fused epilogue: +b1, LIF update, spike, reset
    int row0 = blockIdx.y*BM + trow*TM;
    int col0 = blockIdx.x*BN + tcol*TN;
#pragma unroll
    for (int ii = 0; ii < TM; ii++) {
#pragma unroll
        for (int jj = 0; jj < TN; jj++) {
            int c = col0 + jj;
            size_t idx = (size_t)(row0 + ii) * N + c;
            float h  = __fadd_rn(acc[ii][jj], b1[c]);
            float lm = first ? 0.0f : lif[idx];
            lm = __fadd_rn(lm, __fmul_rn(__fsub_rn(h, lm), 0.5f));
            unsigned char sb = (lm >= 0.5f) ? 1 : 0;
            lif[idx] = sb ? 0.0f : lm;
            hs[idx]  = sb;
        }
    }
}

// ---------------- per-step: out_acc[n,:] += hs[n,:] @ W2 + b2 (warp per row) ----------------
__global__ __launch_bounds__(256)
void out_kernel(const unsigned char* __restrict__ hs, const float* __restrict__ W2,
                const float* __restrict__ b2, float* __restrict__ outacc, int first)
{
    __shared__ float W2s[HID * NLAST];      // 36 KB
    for (int i = threadIdx.x; i < HID * NLAST; i += blockDim.x) W2s[i] = W2[i];
    __syncthreads();

    int warp = threadIdx.x >> 5;
    int lane = threadIdx.x & 31;
    int n = blockIdx.x * 8 + warp;          // grid = BSROWS/8

    uint4 v = ((const uint4*)(hs + (size_t)n * HID))[lane];   // 16 bytes of spikes
    const unsigned char* pb = (const unsigned char*)&v;

    float acc[NLAST];
#pragma unroll
    for (int l = 0; l < NLAST; l++) acc[l] = 0.0f;

#pragma unroll
    for (int jj = 0; jj < 16; jj++) {
        if (pb[jj]) {
            const float* wrow = &W2s[(lane * 16 + jj) * NLAST];
#pragma unroll
            for (int l = 0; l < NLAST; l++) acc[l] += wrow[l];
        }
    }
#pragma unroll
    for (int off = 16; off > 0; off >>= 1)
#pragma unroll
        for (int l = 0; l < NLAST; l++)
            acc[l] += __shfl_down_sync(0xffffffffu, acc[l], off);

    if (lane == 0) {
        float* dst = outacc + (size_t)n * NLAST;
#pragma unroll
        for (int l = 0; l < NLAST; l++) {
            float val = __fadd_rn(acc[l], b2[l]);
            dst[l] = first ? val : __fadd_rn(dst[l], val);
        }
    }
}

// ---------------- final: mean over T, reshape [B,S,L] -> [B,L,S] ----------------
__global__ void final_kernel(const float* __restrict__ outacc, float* __restrict__ out)
{
    int i = blockIdx.x * blockDim.x + threadIdx.x;   // over BATCH*NLAST*SEQ
    if (i >= BATCH * NLAST * SEQ) return;
    int s = i % SEQ;
    int l = (i / SEQ) % NLAST;
    int b = i / (SEQ * NLAST);
    int n = b * SEQ + s;
    out[i] = __fmul_rn(outacc[(size_t)n * NLAST + l], 0.25f);
}

// ---------------- launcher ----------------
extern "C" void kernel_launch(void* const* d_in, const int* in_sizes, int n_in,
                              void* d_out, int out_size)
{
    const float* state = (const float*)d_in[0];   // [4,128,3136]
    const float* tau   = (const float*)d_in[1];   // [4,8192,3136]
    const float* event = (const float*)d_in[2];   // [4,128,3136]
    const float* Wp    = (const float*)d_in[3];   // [3136,512]
    const float* Wd    = (const float*)d_in[4];   // [3136,512]
    const float* Wt    = (const float*)d_in[5];   // [3136,512]
    const float* W1    = (const float*)d_in[6];   // [512,512]
    const float* b1    = (const float*)d_in[7];   // [512]
    const float* W2    = (const float*)d_in[8];   // [512,18]
    const float* b2    = (const float*)d_in[9];   // [18]
    float* out = (float*)d_out;

    // Resolve device-global scratch (queries only; no allocation, capture-safe,
    // deterministic — same result every call).
    float *dist, *prox, *trunk, *p, *ts, *d, *soma, *lif, *outacc;
    unsigned char *spk, *hs;
    cudaGetSymbolAddress((void**)&dist,   g_dist);
    cudaGetSymbolAddress((void**)&prox,   g_prox);
    cudaGetSymbolAddress((void**)&trunk,  g_trunk);
    cudaGetSymbolAddress((void**)&p,      g_p);
    cudaGetSymbolAddress((void**)&ts,     g_ts);
    cudaGetSymbolAddress((void**)&d,      g_d);
    cudaGetSymbolAddress((void**)&soma,   g_soma);
    cudaGetSymbolAddress((void**)&spk,    g_spk);
    cudaGetSymbolAddress((void**)&lif,    g_lif);
    cudaGetSymbolAddress((void**)&hs,     g_hs);
    cudaGetSymbolAddress((void**)&outacc, g_outacc);

    // Hoisted projections (carry-independent)
    {
        dim3 grid(FUS/64, (T_WIN*BSROWS)/128);
        sgemm_kernel<128,64,16,8,4><<<grid, 256>>>(tau, Wd, dist, T_WIN*BSROWS, FUS, DIN);
    }
    {
        dim3 grid(FUS/64, (T_WIN*BATCH)/64);
        sgemm_kernel<64,64,16,4,4><<<grid, 256>>>(state, Wp, prox,  T_WIN*BATCH, FUS, DIN);
        sgemm_kernel<64,64,16,4,4><<<grid, 256>>>(event, Wt, trunk, T_WIN*BATCH, FUS, DIN);
    }

    // Sequential time loop (carry dependence)
    for (int t = 0; t < T_WIN; t++) {
        int first = (t == 0);
        lif_pt_kernel<<<(BATCH*FUS)/256, 256>>>(prox + (size_t)t*BATCH*FUS,
                                                trunk + (size_t)t*BATCH*FUS, p, ts, first);
        lif_soma_kernel<<<(BSROWS*FUS/4)/256, 256>>>(dist + (size_t)t*BSROWS*FUS,
                                                     p, ts, d, soma, spk, first);
        {
            dim3 grid(HID/64, BSROWS/64);
            h_lif_kernel<64,64,32,4,4><<<grid, 256>>>(spk, W1, b1, lif, hs, first);
        }
        out_kernel<<<BSROWS/8, 256>>>(hs, W2, b2, outacc, first);
    }

    final_kernel<<<(BATCH*NLAST*SEQ)/256, 256>>>(outacc, out);
}